// round 1
// baseline (speedup 1.0000x reference)
#include <cuda_runtime.h>
#include <math.h>

#define BATCH 2
#define SEQL 2048
#define HID 1024
#define NHEAD 16
#define HDIM 64
#define MTOT (BATCH * SEQL)   // 4096

// Scratch (allocation-free rule: __device__ globals)
__device__ float g_q[MTOT * HID];
__device__ float g_k[MTOT * HID];
__device__ float g_v[MTOT * HID];
__device__ float g_ctx[MTOT * HID];

// ---------------------------------------------------------------------------
// Tiled SGEMM: C[M,N] = A[M,K] @ B[K,N] + bias[N]
// 128x128 block tile, K-tile 16, 256 threads, 8x8 per-thread microtile.
// M,N multiples of 128; K multiple of 16 (true for all our shapes).
// ---------------------------------------------------------------------------
#define BM 128
#define BN 128
#define BKK 16

__global__ __launch_bounds__(256) void sgemm_bias_kernel(
    const float* __restrict__ A, const float* __restrict__ B,
    const float* __restrict__ bias, float* __restrict__ C,
    int M, int N, int K) {
  __shared__ float As[BKK][BM];
  __shared__ float Bs[BKK][BN];
  const int tid = threadIdx.x;
  const int tx = tid & 15;   // 0..15 -> N subtile
  const int ty = tid >> 4;   // 0..15 -> M subtile
  const int row0 = blockIdx.y * BM;
  const int col0 = blockIdx.x * BN;

  // A tile: 128 rows x 16 cols = 512 float4; thread -> row tid>>2 (+64), f4 col tid&3
  const int ar = tid >> 2;
  const int ac = (tid & 3) * 4;
  // B tile: 16 rows x 128 cols = 512 float4; thread -> row tid>>5 (+8), f4 col tid&31
  const int br = tid >> 5;
  const int bc = (tid & 31) * 4;

  float acc[8][8];
#pragma unroll
  for (int i = 0; i < 8; i++)
#pragma unroll
    for (int j = 0; j < 8; j++) acc[i][j] = 0.f;

  for (int k0 = 0; k0 < K; k0 += BKK) {
#pragma unroll
    for (int i = 0; i < 2; i++) {
      int r = ar + i * 64;
      float4 v = *(const float4*)(A + (size_t)(row0 + r) * K + k0 + ac);
      As[ac + 0][r] = v.x;
      As[ac + 1][r] = v.y;
      As[ac + 2][r] = v.z;
      As[ac + 3][r] = v.w;
    }
#pragma unroll
    for (int i = 0; i < 2; i++) {
      int r = br + i * 8;
      *(float4*)&Bs[r][bc] = *(const float4*)(B + (size_t)(k0 + r) * N + col0 + bc);
    }
    __syncthreads();
#pragma unroll
    for (int kk = 0; kk < BKK; kk++) {
      float af[8], bf[8];
#pragma unroll
      for (int i = 0; i < 8; i++) af[i] = As[kk][ty * 8 + i];
#pragma unroll
      for (int j = 0; j < 8; j++) bf[j] = Bs[kk][tx * 8 + j];
#pragma unroll
      for (int i = 0; i < 8; i++)
#pragma unroll
        for (int j = 0; j < 8; j++) acc[i][j] = fmaf(af[i], bf[j], acc[i][j]);
    }
    __syncthreads();
  }

#pragma unroll
  for (int i = 0; i < 8; i++) {
    int row = row0 + ty * 8 + i;
#pragma unroll
    for (int j = 0; j < 8; j += 4) {
      int col = col0 + tx * 8 + j;
      float4 bb = *(const float4*)(bias + col);
      float4 ov = make_float4(acc[i][j] + bb.x, acc[i][j + 1] + bb.y,
                              acc[i][j + 2] + bb.z, acc[i][j + 3] + bb.w);
      *(float4*)(C + (size_t)row * N + col) = ov;
    }
  }
}

// ---------------------------------------------------------------------------
// Flash-style attention. Grid: (SEQ/128, NHEAD, BATCH), 128 threads.
// Thread t owns query s = blk*128 + t. q[64] and o[64] live in registers.
// K/V tiles of 128 keys staged in shared memory; chunked online softmax
// (16 keys per chunk -> one o-rescale per chunk).
// Layout of Q/K/V: [b*SEQ + s][h*64 + d] (projection output, row-major).
// Output written in concat layout [b*SEQ + s][h*64 + d].
// ---------------------------------------------------------------------------
#define KV_TILE 128

__global__ __launch_bounds__(128, 2) void attn_kernel(
    const float* __restrict__ Qg, const float* __restrict__ Kg,
    const float* __restrict__ Vg, float* __restrict__ Og) {
  const int h = blockIdx.y;
  const int b = blockIdx.z;
  const int tid = threadIdx.x;
  const int s = blockIdx.x * 128 + tid;

  __shared__ float Ks[KV_TILE][HDIM];
  __shared__ float Vs[KV_TILE][HDIM];

  const size_t rowQ = (size_t)(b * SEQL + s) * HID + h * HDIM;
  float q[HDIM];
#pragma unroll
  for (int d = 0; d < HDIM; d += 4) {
    float4 t = *(const float4*)(Qg + rowQ + d);
    q[d] = t.x; q[d + 1] = t.y; q[d + 2] = t.z; q[d + 3] = t.w;
  }

  const float scale = 0.125f;  // 1/sqrt(64)
  float m = -1e30f, l = 0.f;
  float o[HDIM];
#pragma unroll
  for (int d = 0; d < HDIM; d++) o[d] = 0.f;

  for (int kb = 0; kb < SEQL; kb += KV_TILE) {
    __syncthreads();
    // cooperative tile load: KV_TILE rows x 16 float4 each
    for (int i = tid; i < KV_TILE * (HDIM / 4); i += 128) {
      int r = i >> 4;
      int c = (i & 15) * 4;
      size_t g = (size_t)(b * SEQL + kb + r) * HID + h * HDIM + c;
      *(float4*)&Ks[r][c] = *(const float4*)(Kg + g);
      *(float4*)&Vs[r][c] = *(const float4*)(Vg + g);
    }
    __syncthreads();

#pragma unroll 1
    for (int jc = 0; jc < KV_TILE; jc += 16) {
      float sv[16];
#pragma unroll
      for (int j = 0; j < 16; j++) {
        float4 a4 = make_float4(0.f, 0.f, 0.f, 0.f);
#pragma unroll
        for (int d = 0; d < HDIM; d += 4) {
          float4 kk = *(const float4*)&Ks[jc + j][d];
          a4.x = fmaf(q[d], kk.x, a4.x);
          a4.y = fmaf(q[d + 1], kk.y, a4.y);
          a4.z = fmaf(q[d + 2], kk.z, a4.z);
          a4.w = fmaf(q[d + 3], kk.w, a4.w);
        }
        sv[j] = (a4.x + a4.y + a4.z + a4.w) * scale;
      }
      float cmax = m;
#pragma unroll
      for (int j = 0; j < 16; j++) cmax = fmaxf(cmax, sv[j]);
      float fac = __expf(m - cmax);  // exp(-huge)=0 on first chunk: safe
      m = cmax;
      l *= fac;
#pragma unroll
      for (int d = 0; d < HDIM; d++) o[d] *= fac;
#pragma unroll
      for (int j = 0; j < 16; j++) {
        float p = __expf(sv[j] - m);
        l += p;
#pragma unroll
        for (int d = 0; d < HDIM; d += 4) {
          float4 vv = *(const float4*)&Vs[jc + j][d];
          o[d]     = fmaf(p, vv.x, o[d]);
          o[d + 1] = fmaf(p, vv.y, o[d + 1]);
          o[d + 2] = fmaf(p, vv.z, o[d + 2]);
          o[d + 3] = fmaf(p, vv.w, o[d + 3]);
        }
      }
    }
  }

  const float inv = 1.f / l;
  const size_t rowO = (size_t)(b * SEQL + s) * HID + h * HDIM;
#pragma unroll
  for (int d = 0; d < HDIM; d += 4) {
    float4 t = make_float4(o[d] * inv, o[d + 1] * inv, o[d + 2] * inv, o[d + 3] * inv);
    *(float4*)(Og + rowO + d) = t;
  }
}

// ---------------------------------------------------------------------------
extern "C" void kernel_launch(void* const* d_in, const int* in_sizes, int n_in,
                              void* d_out, int out_size) {
  const float* x  = (const float*)d_in[0];
  const float* Wq = (const float*)d_in[1];
  const float* bq = (const float*)d_in[2];
  const float* Wk = (const float*)d_in[3];
  const float* bk = (const float*)d_in[4];
  const float* Wv = (const float*)d_in[5];
  const float* bv = (const float*)d_in[6];
  const float* Wo = (const float*)d_in[7];
  const float* bo = (const float*)d_in[8];
  float* out = (float*)d_out;

  float *q, *k, *v, *ctx;
  cudaGetSymbolAddress((void**)&q, g_q);
  cudaGetSymbolAddress((void**)&k, g_k);
  cudaGetSymbolAddress((void**)&v, g_v);
  cudaGetSymbolAddress((void**)&ctx, g_ctx);

  dim3 gblk(256);
  dim3 ggrid(HID / BN, MTOT / BM);  // (8, 32)

  sgemm_bias_kernel<<<ggrid, gblk>>>(x, Wq, bq, q, MTOT, HID, HID);
  sgemm_bias_kernel<<<ggrid, gblk>>>(x, Wk, bk, k, MTOT, HID, HID);
  sgemm_bias_kernel<<<ggrid, gblk>>>(x, Wv, bv, v, MTOT, HID, HID);

  dim3 agrid(SEQL / 128, NHEAD, BATCH);  // (16, 16, 2)
  attn_kernel<<<agrid, 128>>>(q, k, v, ctx);

  sgemm_bias_kernel<<<ggrid, gblk>>>(ctx, Wo, bo, out, MTOT, HID, HID);
}

// round 3
// speedup vs baseline: 1.3477x; 1.3477x over previous
#include <cuda_runtime.h>
#include <cuda_bf16.h>
#include <math.h>
#include <stdint.h>

#define BATCH 2
#define SEQL 2048
#define HID 1024
#define NHEAD 16
#define HDIM 64
#define MTOT (BATCH * SEQL)   // 4096

// ---------------------------------------------------------------------------
// Scratch (__device__ globals; allocation-free rule)
// ---------------------------------------------------------------------------
__device__ float g_q[MTOT * HID];
__device__ float g_k[MTOT * HID];
__device__ float g_v[MTOT * HID];
__device__ float g_ctx[MTOT * HID];
__device__ __nv_bfloat16 g_xh[MTOT * HID], g_xl[MTOT * HID];
__device__ __nv_bfloat16 g_ch[MTOT * HID], g_cl[MTOT * HID];
__device__ __nv_bfloat16 g_Wqh[HID * HID], g_Wql[HID * HID];
__device__ __nv_bfloat16 g_Wkh[HID * HID], g_Wkl[HID * HID];
__device__ __nv_bfloat16 g_Wvh[HID * HID], g_Wvl[HID * HID];
__device__ __nv_bfloat16 g_Woh[HID * HID], g_Wol[HID * HID];

// ---------------------------------------------------------------------------
// PTX helpers (arch-neutral: ldmatrix / mma.sync / cp.async only)
// ---------------------------------------------------------------------------
__device__ __forceinline__ uint32_t smem_u32(const void* p) {
  uint32_t a;
  asm("{ .reg .u64 t; cvta.to.shared.u64 t, %1; cvt.u32.u64 %0, t; }"
      : "=r"(a) : "l"(p));
  return a;
}

__device__ __forceinline__ void ldm4(uint32_t* d, uint32_t addr) {
  asm volatile(
      "ldmatrix.sync.aligned.m8n8.x4.shared.b16 {%0,%1,%2,%3}, [%4];"
      : "=r"(d[0]), "=r"(d[1]), "=r"(d[2]), "=r"(d[3]) : "r"(addr));
}

__device__ __forceinline__ void mma_bf16(float* d, const uint32_t* a,
                                         uint32_t b0, uint32_t b1) {
  asm volatile(
      "mma.sync.aligned.m16n8k16.row.col.f32.bf16.bf16.f32 "
      "{%0,%1,%2,%3}, {%4,%5,%6,%7}, {%8,%9}, {%0,%1,%2,%3};"
      : "+f"(d[0]), "+f"(d[1]), "+f"(d[2]), "+f"(d[3])
      : "r"(a[0]), "r"(a[1]), "r"(a[2]), "r"(a[3]), "r"(b0), "r"(b1));
}

__device__ __forceinline__ void cp16(uint32_t dst, const void* src) {
  asm volatile("cp.async.cg.shared.global [%0], [%1], 16;"
               :: "r"(dst), "l"(src));
}
#define CP_COMMIT() asm volatile("cp.async.commit_group;" ::: "memory")
#define CP_WAIT1() asm volatile("cp.async.wait_group 1;" ::: "memory")
#define CP_WAIT0() asm volatile("cp.async.wait_group 0;" ::: "memory")

// ---------------------------------------------------------------------------
// Prep: W fp32 [K,N] -> bf16 hi/lo [N,K] (split + transpose)
// ---------------------------------------------------------------------------
__global__ void wsplit_kernel(const float* __restrict__ W,
                              __nv_bfloat16* __restrict__ Wh,
                              __nv_bfloat16* __restrict__ Wl) {
  __shared__ float tile[32][33];
  const int bx = blockIdx.x * 32;  // n block
  const int by = blockIdx.y * 32;  // k block
  const int tx = threadIdx.x, ty = threadIdx.y;
#pragma unroll
  for (int i = 0; i < 32; i += 8)
    tile[ty + i][tx] = W[(size_t)(by + ty + i) * HID + bx + tx];
  __syncthreads();
#pragma unroll
  for (int i = 0; i < 32; i += 8) {
    int n = bx + ty + i, k = by + tx;
    float v = tile[tx][ty + i];
    __nv_bfloat16 h = __float2bfloat16(v);
    Wh[(size_t)n * HID + k] = h;
    Wl[(size_t)n * HID + k] = __float2bfloat16(v - __bfloat162float(h));
  }
}

// Prep: A fp32 [M,K] -> bf16 hi/lo [M,K] (elementwise split)
__global__ __launch_bounds__(256) void asplit_kernel(
    const float* __restrict__ A, __nv_bfloat16* __restrict__ Ah,
    __nv_bfloat16* __restrict__ Al) {
  const int i = (blockIdx.x * 256 + threadIdx.x) * 4;
  float4 v = *(const float4*)(A + i);
  __nv_bfloat16 h0 = __float2bfloat16(v.x), h1 = __float2bfloat16(v.y);
  __nv_bfloat16 h2 = __float2bfloat16(v.z), h3 = __float2bfloat16(v.w);
  __nv_bfloat162 hp0 = __halves2bfloat162(h0, h1);
  __nv_bfloat162 hp1 = __halves2bfloat162(h2, h3);
  __nv_bfloat162 lp0 = __floats2bfloat162_rn(v.x - __bfloat162float(h0),
                                             v.y - __bfloat162float(h1));
  __nv_bfloat162 lp1 = __floats2bfloat162_rn(v.z - __bfloat162float(h2),
                                             v.w - __bfloat162float(h3));
  *(uint2*)(Ah + i) = make_uint2(*(uint32_t*)&hp0, *(uint32_t*)&hp1);
  *(uint2*)(Al + i) = make_uint2(*(uint32_t*)&lp0, *(uint32_t*)&lp1);
}

// ---------------------------------------------------------------------------
// HMMA split GEMM: C[4096,1024] = (Ah+Al)[M,K] @ (Bh+Bl)^T[N,K] + bias
// CTA: 128x128 tile, 256 thr (8 warps x 32x64), KC=64, cp.async 2-stage.
// 3-term: Ah*Bh + Al*Bh + Ah*Bl (fp32 accum).
// ---------------------------------------------------------------------------
#define KC 64
#define TILE16K 16384          // 128 rows x 128B (KC bf16)
#define STAGEB (4 * TILE16K)   // 64KB
#define GSMEM (2 * STAGEB)     // 128KB

__device__ __forceinline__ void stage_load(
    uint32_t sm, const __nv_bfloat16* __restrict__ Ah,
    const __nv_bfloat16* __restrict__ Al, const __nv_bfloat16* __restrict__ Bh,
    const __nv_bfloat16* __restrict__ Bl, int row0, int col0, int k0, int tid) {
#pragma unroll
  for (int it = 0; it < 4; it++) {
    int idx = tid + it * 256;
    int r = idx >> 3, cb = idx & 7;
    uint32_t sw = (uint32_t)(r * 128 + ((cb ^ (r & 7)) << 4));
    size_t ga = (size_t)(row0 + r) * HID + k0 + cb * 8;
    size_t gb = (size_t)(col0 + r) * HID + k0 + cb * 8;
    cp16(sm + sw, Ah + ga);
    cp16(sm + TILE16K + sw, Al + ga);
    cp16(sm + 2 * TILE16K + sw, Bh + gb);
    cp16(sm + 3 * TILE16K + sw, Bl + gb);
  }
}

__device__ __forceinline__ void compute_stage(uint32_t sm, float acc[2][8][4],
                                              int wm0, int wn0, int lane) {
  const uint32_t smAh = sm;
  const uint32_t smAl = sm + TILE16K;
  const uint32_t smBh = sm + 2 * TILE16K;
  const uint32_t smBl = sm + 3 * TILE16K;
#pragma unroll
  for (int ks = 0; ks < 4; ks++) {
    const int cb = ks * 2 + (lane >> 4);
    uint32_t ah[2][4], al[2][4], bh[4][4], bl[4][4];
#pragma unroll
    for (int mi = 0; mi < 2; mi++) {
      int row = wm0 + mi * 16 + (lane & 15);
      uint32_t off = (uint32_t)(row * 128 + ((cb ^ (row & 7)) << 4));
      ldm4(ah[mi], smAh + off);
      ldm4(al[mi], smAl + off);
    }
#pragma unroll
    for (int ni = 0; ni < 4; ni++) {
      int row = wn0 + ni * 16 + (lane & 15);
      uint32_t off = (uint32_t)(row * 128 + ((cb ^ (row & 7)) << 4));
      ldm4(bh[ni], smBh + off);
      ldm4(bl[ni], smBl + off);
    }
#pragma unroll
    for (int mi = 0; mi < 2; mi++)
#pragma unroll
      for (int ni = 0; ni < 4; ni++) {
        mma_bf16(acc[mi][2 * ni], ah[mi], bh[ni][0], bh[ni][2]);
        mma_bf16(acc[mi][2 * ni], al[mi], bh[ni][0], bh[ni][2]);
        mma_bf16(acc[mi][2 * ni], ah[mi], bl[ni][0], bl[ni][2]);
        mma_bf16(acc[mi][2 * ni + 1], ah[mi], bh[ni][1], bh[ni][3]);
        mma_bf16(acc[mi][2 * ni + 1], al[mi], bh[ni][1], bh[ni][3]);
        mma_bf16(acc[mi][2 * ni + 1], ah[mi], bl[ni][1], bl[ni][3]);
      }
  }
}

__global__ __launch_bounds__(256, 1) void gemm_hmma(
    const __nv_bfloat16* __restrict__ Ah, const __nv_bfloat16* __restrict__ Al,
    const __nv_bfloat16* __restrict__ Bh, const __nv_bfloat16* __restrict__ Bl,
    const float* __restrict__ bias, float* __restrict__ C) {
  extern __shared__ char smem[];
  const uint32_t sb = smem_u32(smem);
  const int tid = threadIdx.x;
  const int wid = tid >> 5, lane = tid & 31;
  const int wm0 = (wid & 3) * 32;
  const int wn0 = (wid >> 2) * 64;
  const int row0 = blockIdx.y * 128;
  const int col0 = blockIdx.x * 128;

  float acc[2][8][4];
#pragma unroll
  for (int a = 0; a < 2; a++)
#pragma unroll
    for (int b = 0; b < 8; b++)
#pragma unroll
      for (int c = 0; c < 4; c++) acc[a][b][c] = 0.f;

  stage_load(sb, Ah, Al, Bh, Bl, row0, col0, 0, tid);
  CP_COMMIT();

#pragma unroll 1
  for (int c = 0; c < HID / KC; c++) {
    if (c < HID / KC - 1) {
      stage_load(sb + ((c + 1) & 1) * STAGEB, Ah, Al, Bh, Bl, row0, col0,
                 (c + 1) * KC, tid);
      CP_COMMIT();
      CP_WAIT1();
    } else {
      CP_WAIT0();
    }
    __syncthreads();
    compute_stage(sb + (c & 1) * STAGEB, acc, wm0, wn0, lane);
    __syncthreads();
  }

  // Epilogue: + bias, store fp32
  const int g = lane >> 2;
  const int q2 = (lane & 3) * 2;
#pragma unroll
  for (int mi = 0; mi < 2; mi++) {
#pragma unroll
    for (int ni = 0; ni < 8; ni++) {
      int r0 = row0 + wm0 + mi * 16 + g;
      int col = col0 + wn0 + ni * 8 + q2;
      float2 bb = *(const float2*)(bias + col);
      float2 v0 = make_float2(acc[mi][ni][0] + bb.x, acc[mi][ni][1] + bb.y);
      float2 v1 = make_float2(acc[mi][ni][2] + bb.x, acc[mi][ni][3] + bb.y);
      *(float2*)(C + (size_t)r0 * HID + col) = v0;
      *(float2*)(C + (size_t)(r0 + 8) * HID + col) = v1;
    }
  }
}

// ---------------------------------------------------------------------------
// Flash-style scalar attention (unchanged from R1 passing version)
// ---------------------------------------------------------------------------
#define KV_TILE 128

__global__ __launch_bounds__(128, 2) void attn_kernel(
    const float* __restrict__ Qg, const float* __restrict__ Kg,
    const float* __restrict__ Vg, float* __restrict__ Og) {
  const int h = blockIdx.y;
  const int b = blockIdx.z;
  const int tid = threadIdx.x;
  const int s = blockIdx.x * 128 + tid;

  __shared__ float Ks[KV_TILE][HDIM];
  __shared__ float Vs[KV_TILE][HDIM];

  const size_t rowQ = (size_t)(b * SEQL + s) * HID + h * HDIM;
  float q[HDIM];
#pragma unroll
  for (int d = 0; d < HDIM; d += 4) {
    float4 t = *(const float4*)(Qg + rowQ + d);
    q[d] = t.x; q[d + 1] = t.y; q[d + 2] = t.z; q[d + 3] = t.w;
  }

  const float scale = 0.125f;
  float m = -1e30f, l = 0.f;
  float o[HDIM];
#pragma unroll
  for (int d = 0; d < HDIM; d++) o[d] = 0.f;

  for (int kb = 0; kb < SEQL; kb += KV_TILE) {
    __syncthreads();
    for (int i = tid; i < KV_TILE * (HDIM / 4); i += 128) {
      int r = i >> 4;
      int c = (i & 15) * 4;
      size_t g = (size_t)(b * SEQL + kb + r) * HID + h * HDIM + c;
      *(float4*)&Ks[r][c] = *(const float4*)(Kg + g);
      *(float4*)&Vs[r][c] = *(const float4*)(Vg + g);
    }
    __syncthreads();

#pragma unroll 1
    for (int jc = 0; jc < KV_TILE; jc += 16) {
      float sv[16];
#pragma unroll
      for (int j = 0; j < 16; j++) {
        float4 a4 = make_float4(0.f, 0.f, 0.f, 0.f);
#pragma unroll
        for (int d = 0; d < HDIM; d += 4) {
          float4 kk = *(const float4*)&Ks[jc + j][d];
          a4.x = fmaf(q[d], kk.x, a4.x);
          a4.y = fmaf(q[d + 1], kk.y, a4.y);
          a4.z = fmaf(q[d + 2], kk.z, a4.z);
          a4.w = fmaf(q[d + 3], kk.w, a4.w);
        }
        sv[j] = (a4.x + a4.y + a4.z + a4.w) * scale;
      }
      float cmax = m;
#pragma unroll
      for (int j = 0; j < 16; j++) cmax = fmaxf(cmax, sv[j]);
      float fac = __expf(m - cmax);
      m = cmax;
      l *= fac;
#pragma unroll
      for (int d = 0; d < HDIM; d++) o[d] *= fac;
#pragma unroll
      for (int j = 0; j < 16; j++) {
        float p = __expf(sv[j] - m);
        l += p;
#pragma unroll
        for (int d = 0; d < HDIM; d += 4) {
          float4 vv = *(const float4*)&Vs[jc + j][d];
          o[d]     = fmaf(p, vv.x, o[d]);
          o[d + 1] = fmaf(p, vv.y, o[d + 1]);
          o[d + 2] = fmaf(p, vv.z, o[d + 2]);
          o[d + 3] = fmaf(p, vv.w, o[d + 3]);
        }
      }
    }
  }

  const float inv = 1.f / l;
  const size_t rowO = (size_t)(b * SEQL + s) * HID + h * HDIM;
#pragma unroll
  for (int d = 0; d < HDIM; d += 4) {
    float4 t = make_float4(o[d] * inv, o[d + 1] * inv, o[d + 2] * inv, o[d + 3] * inv);
    *(float4*)(Og + rowO + d) = t;
  }
}

// ---------------------------------------------------------------------------
extern "C" void kernel_launch(void* const* d_in, const int* in_sizes, int n_in,
                              void* d_out, int out_size) {
  const float* x  = (const float*)d_in[0];
  const float* Wq = (const float*)d_in[1];
  const float* bq = (const float*)d_in[2];
  const float* Wk = (const float*)d_in[3];
  const float* bk = (const float*)d_in[4];
  const float* Wv = (const float*)d_in[5];
  const float* bv = (const float*)d_in[6];
  const float* Wo = (const float*)d_in[7];
  const float* bo = (const float*)d_in[8];
  float* out = (float*)d_out;

  float *q, *k, *v, *ctx;
  cudaGetSymbolAddress((void**)&q, g_q);
  cudaGetSymbolAddress((void**)&k, g_k);
  cudaGetSymbolAddress((void**)&v, g_v);
  cudaGetSymbolAddress((void**)&ctx, g_ctx);
  __nv_bfloat16 *xh, *xl, *ch, *cl;
  cudaGetSymbolAddress((void**)&xh, g_xh);
  cudaGetSymbolAddress((void**)&xl, g_xl);
  cudaGetSymbolAddress((void**)&ch, g_ch);
  cudaGetSymbolAddress((void**)&cl, g_cl);
  __nv_bfloat16 *wqh, *wql, *wkh, *wkl, *wvh, *wvl, *woh, *wol;
  cudaGetSymbolAddress((void**)&wqh, g_Wqh);
  cudaGetSymbolAddress((void**)&wql, g_Wql);
  cudaGetSymbolAddress((void**)&wkh, g_Wkh);
  cudaGetSymbolAddress((void**)&wkl, g_Wkl);
  cudaGetSymbolAddress((void**)&wvh, g_Wvh);
  cudaGetSymbolAddress((void**)&wvl, g_Wvl);
  cudaGetSymbolAddress((void**)&woh, g_Woh);
  cudaGetSymbolAddress((void**)&wol, g_Wol);

  cudaFuncSetAttribute(gemm_hmma, cudaFuncAttributeMaxDynamicSharedMemorySize,
                       GSMEM);

  dim3 tb(32, 8);
  dim3 tg(32, 32);
  wsplit_kernel<<<tg, tb>>>(Wq, wqh, wql);
  wsplit_kernel<<<tg, tb>>>(Wk, wkh, wkl);
  wsplit_kernel<<<tg, tb>>>(Wv, wvh, wvl);
  wsplit_kernel<<<tg, tb>>>(Wo, woh, wol);
  asplit_kernel<<<MTOT * HID / 1024, 256>>>(x, xh, xl);

  dim3 ggrid(HID / 128, MTOT / 128);  // (8, 32)
  gemm_hmma<<<ggrid, 256, GSMEM>>>(xh, xl, wqh, wql, bq, q);
  gemm_hmma<<<ggrid, 256, GSMEM>>>(xh, xl, wkh, wkl, bk, k);
  gemm_hmma<<<ggrid, 256, GSMEM>>>(xh, xl, wvh, wvl, bv, v);

  dim3 agrid(SEQL / 128, NHEAD, BATCH);
  attn_kernel<<<agrid, 128>>>(q, k, v, ctx);

  asplit_kernel<<<MTOT * HID / 1024, 256>>>(ctx, ch, cl);
  gemm_hmma<<<ggrid, 256, GSMEM>>>(ch, cl, woh, wol, bo, out);
}